// round 5
// baseline (speedup 1.0000x reference)
#include <cuda_runtime.h>
#include <cuda_bf16.h>
#include <stdint.h>

#define N_NODES 100000
#define N_FEAT  512
#define N_HID   128
#define N_CLASS 40

// ---------------- scratch (device globals; no allocations allowed) ----------
__device__ float g_xw1[(size_t)N_NODES * N_HID];    // X @ W1
__device__ float g_h  [(size_t)N_NODES * N_HID];    // spmm1 accum -> hidden
__device__ float g_hw2[(size_t)N_NODES * N_CLASS];  // h @ W2

// ---------------- Threefry-2x32-20 -----------------------------------------
__device__ __forceinline__ uint32_t rotl32(uint32_t x, int d) {
    return __funnelshift_l(x, x, d);
}

__device__ __forceinline__ uint2 threefry2x32(uint32_t k0, uint32_t k1,
                                              uint32_t x0, uint32_t x1) {
    uint32_t ks2 = k0 ^ k1 ^ 0x1BD11BDAu;
    x0 += k0; x1 += k1;
#define TF_MIX(r) { x0 += x1; x1 = rotl32(x1, r); x1 ^= x0; }
    TF_MIX(13) TF_MIX(15) TF_MIX(26) TF_MIX(6)   x0 += k1;  x1 += ks2 + 1u;
    TF_MIX(17) TF_MIX(29) TF_MIX(16) TF_MIX(24)  x0 += ks2; x1 += k0 + 2u;
    TF_MIX(13) TF_MIX(15) TF_MIX(26) TF_MIX(6)   x0 += k0;  x1 += k1 + 3u;
    TF_MIX(17) TF_MIX(29) TF_MIX(16) TF_MIX(24)  x0 += k1;  x1 += ks2 + 4u;
    TF_MIX(13) TF_MIX(15) TF_MIX(26) TF_MIX(6)   x0 += ks2; x1 += k0 + 5u;
#undef TF_MIX
    return make_uint2(x0, x1);
}

// ---------------- vectorized global f32x4 reduction -------------------------
__device__ __forceinline__ void red_add_v4(float* p, float4 v) {
    asm volatile("red.global.add.v4.f32 [%0], {%1, %2, %3, %4};"
                 :: "l"(p), "f"(v.x), "f"(v.y), "f"(v.z), "f"(v.w)
                 : "memory");
}

// ---------------- GEMM1: [M,512] @ [512,128] -> [M,128] ---------------------
__global__ __launch_bounds__(256) void gemm1_kernel(
    const float* __restrict__ A, const float* __restrict__ B,
    float* __restrict__ C, int M) {
    const int K = N_FEAT, N = N_HID;
    __shared__ float As[8][128];
    __shared__ float Bs[8][128];

    int row0 = blockIdx.x * 128;
    int tid = threadIdx.x;
    int tr = tid >> 4;       // 0..15
    int tc = tid & 15;       // 0..15

    float acc[8][8];
#pragma unroll
    for (int i = 0; i < 8; i++)
#pragma unroll
        for (int j = 0; j < 8; j++) acc[i][j] = 0.f;

    for (int k0 = 0; k0 < K; k0 += 8) {
#pragma unroll
        for (int i = 0; i < 4; i++) {
            int idx = tid + i * 256;
            int m = idx >> 3, k = idx & 7;
            int gr = row0 + m;
            As[k][m] = (gr < M) ? A[(size_t)gr * K + k0 + k] : 0.f;
        }
        {
            int k = tid >> 5, n4 = tid & 31;
            float4 v = ((const float4*)(B + (size_t)(k0 + k) * N))[n4];
            ((float4*)&Bs[k][0])[n4] = v;
        }
        __syncthreads();
#pragma unroll
        for (int k = 0; k < 8; k++) {
            float4 a0 = ((const float4*)&As[k][tr * 8])[0];
            float4 a1 = ((const float4*)&As[k][tr * 8])[1];
            float4 b0 = ((const float4*)&Bs[k][tc * 8])[0];
            float4 b1 = ((const float4*)&Bs[k][tc * 8])[1];
            float ra[8] = {a0.x, a0.y, a0.z, a0.w, a1.x, a1.y, a1.z, a1.w};
            float rb[8] = {b0.x, b0.y, b0.z, b0.w, b1.x, b1.y, b1.z, b1.w};
#pragma unroll
            for (int i = 0; i < 8; i++)
#pragma unroll
                for (int j = 0; j < 8; j++) acc[i][j] += ra[i] * rb[j];
        }
        __syncthreads();
    }
#pragma unroll
    for (int i = 0; i < 8; i++) {
        int gr = row0 + tr * 8 + i;
        if (gr < M) {
            float4 o0 = make_float4(acc[i][0], acc[i][1], acc[i][2], acc[i][3]);
            float4 o1 = make_float4(acc[i][4], acc[i][5], acc[i][6], acc[i][7]);
            float4* cp = (float4*)(C + (size_t)gr * N + tc * 8);
            cp[0] = o0; cp[1] = o1;
        }
    }
}

// ---------------- SpMM D=128: one warp per edge, red.v4 per lane ------------
__global__ __launch_bounds__(256) void spmm128_kernel(
    const int* __restrict__ src, const int* __restrict__ dst,
    const float* __restrict__ w, const float* __restrict__ x,
    float* __restrict__ y, int E) {
    long long t = (long long)blockIdx.x * blockDim.x + threadIdx.x;
    int e = (int)(t >> 5);
    if (e >= E) return;
    int p = (int)(t & 31);
    float wt = w[e];
    int s = src[e], d = dst[e];
    float4 v = __ldg((const float4*)(x + (size_t)s * N_HID) + p);
    v.x *= wt; v.y *= wt; v.z *= wt; v.w *= wt;
    red_add_v4(y + (size_t)d * N_HID + p * 4, v);
}

// ---------------- bias + relu + dropout ------------------------------------
// Verified scheme (R4 oracle): bits = threefry2x32(0, 42, 0, idx).x
__global__ __launch_bounds__(256) void brd_kernel(
    float* __restrict__ h, const float* __restrict__ b1, int total) {
    int idx = blockIdx.x * blockDim.x + threadIdx.x;
    if (idx >= total) return;
    int j = idx & (N_HID - 1);
    float v = h[idx] + b1[j];
    v = fmaxf(v, 0.f);

    uint2 r = threefry2x32(0u, 42u, 0u, (uint32_t)idx);
    uint32_t bits = r.x;

    float u = __uint_as_float((bits >> 9) | 0x3f800000u) - 1.0f;
    h[idx] = (u < 0.5f) ? v * 2.0f : 0.0f;
}

// ---------------- GEMM2: [M,128] @ [128,40] -> [M,40] -----------------------
__global__ __launch_bounds__(256) void gemm2_kernel(
    const float* __restrict__ H, const float* __restrict__ W2,
    float* __restrict__ out, int M) {
    __shared__ float Ws[N_HID * N_CLASS];
    for (int i = threadIdx.x; i < N_HID * N_CLASS; i += 256) Ws[i] = W2[i];
    __syncthreads();
    long long t = (long long)blockIdx.x * 256 + threadIdx.x;
    if (t >= (long long)M * N_CLASS) return;
    int n = (int)(t / N_CLASS), c = (int)(t % N_CLASS);
    const float* hr = H + (size_t)n * N_HID;
    float s = 0.f;
#pragma unroll
    for (int k = 0; k < N_HID; k++) s += hr[k] * Ws[k * N_CLASS + c];
    out[t] = s;
}

// ---------------- SpMM D=40: thread per (edge, float4 chunk) ----------------
__global__ __launch_bounds__(256) void spmm40_kernel(
    const int* __restrict__ src, const int* __restrict__ dst,
    const float* __restrict__ w, const float* __restrict__ x,
    float* __restrict__ y, int E) {
    long long t = (long long)blockIdx.x * blockDim.x + threadIdx.x;
    if (t >= (long long)E * 10) return;
    int e = (int)(t / 10);
    int c4 = (int)(t % 10);
    float wt = w[e];
    int s = src[e], d = dst[e];
    float4 v = __ldg((const float4*)(x + (size_t)s * N_CLASS) + c4);
    v.x *= wt; v.y *= wt; v.z *= wt; v.w *= wt;
    red_add_v4(y + (size_t)d * N_CLASS + c4 * 4, v);
}

// ---------------- bias + log_softmax (one warp per node) --------------------
__global__ __launch_bounds__(256) void lsm_kernel(
    float* __restrict__ out, const float* __restrict__ b2, int M) {
    int node = blockIdx.x * 8 + (threadIdx.x >> 5);
    int lane = threadIdx.x & 31;
    if (node >= M) return;
    float* row = out + (size_t)node * N_CLASS;
    float v0 = row[lane] + b2[lane];
    float v1 = (lane < N_CLASS - 32) ? row[32 + lane] + b2[32 + lane] : -3.402823466e38f;
    float m = fmaxf(v0, v1);
#pragma unroll
    for (int o = 16; o > 0; o >>= 1) m = fmaxf(m, __shfl_xor_sync(0xffffffffu, m, o));
    float s = expf(v0 - m) + ((lane < N_CLASS - 32) ? expf(v1 - m) : 0.f);
#pragma unroll
    for (int o = 16; o > 0; o >>= 1) s += __shfl_xor_sync(0xffffffffu, s, o);
    float lse = m + logf(s);
    row[lane] = v0 - lse;
    if (lane < N_CLASS - 32) row[32 + lane] = v1 - lse;
}

// ---------------- launcher ---------------------------------------------------
extern "C" void kernel_launch(void* const* d_in, const int* in_sizes, int n_in,
                              void* d_out, int out_size) {
    const float* feature = (const float*)d_in[0];
    const int*   esrc    = (const int*)d_in[1];
    const int*   edst    = (const int*)d_in[2];
    const float* ew      = (const float*)d_in[3];
    const float* W1      = (const float*)d_in[4];
    const float* b1      = (const float*)d_in[5];
    const float* W2      = (const float*)d_in[6];
    const float* b2      = (const float*)d_in[7];
    float* out = (float*)d_out;

    int M = in_sizes[0] / N_FEAT;   // 100000
    int E = in_sizes[1];            // 3200000

    float *xw1, *h, *hw2;
    cudaGetSymbolAddress((void**)&xw1, g_xw1);
    cudaGetSymbolAddress((void**)&h,   g_h);
    cudaGetSymbolAddress((void**)&hw2, g_hw2);

    // layer 1
    gemm1_kernel<<<(M + 127) / 128, 256>>>(feature, W1, xw1, M);
    cudaMemsetAsync(h, 0, sizeof(float) * (size_t)M * N_HID, 0);
    {
        long long work = (long long)E * 32;
        int blocks = (int)((work + 255) / 256);
        spmm128_kernel<<<blocks, 256>>>(esrc, edst, ew, xw1, h, E);
    }
    brd_kernel<<<(M * N_HID + 255) / 256, 256>>>(h, b1, M * N_HID);

    // layer 2
    {
        long long work = (long long)M * N_CLASS;
        gemm2_kernel<<<(int)((work + 255) / 256), 256>>>(h, W2, hw2, M);
    }
    cudaMemsetAsync(out, 0, sizeof(float) * (size_t)M * N_CLASS, 0);
    {
        long long work = (long long)E * 10;
        spmm40_kernel<<<(int)((work + 255) / 256), 256>>>(esrc, edst, ew, hw2, out, E);
    }
    lsm_kernel<<<(M + 7) / 8, 256>>>(out, b2, M);
}

// round 6
// speedup vs baseline: 1.1661x; 1.1661x over previous
#include <cuda_runtime.h>
#include <cuda_bf16.h>
#include <stdint.h>

#define N_NODES 100000
#define N_FEAT  512
#define N_HID   128
#define N_CLASS 40

// ---------------- scratch (device globals; no allocations allowed) ----------
__device__ float g_xw1[(size_t)N_NODES * N_HID];    // X @ W1
__device__ float g_h  [(size_t)N_NODES * N_HID];    // spmm1 accum -> hidden
__device__ float g_hw2[(size_t)N_NODES * N_CLASS];  // h @ W2

// ---------------- Threefry-2x32-20 -----------------------------------------
__device__ __forceinline__ uint32_t rotl32(uint32_t x, int d) {
    return __funnelshift_l(x, x, d);
}

__device__ __forceinline__ uint2 threefry2x32(uint32_t k0, uint32_t k1,
                                              uint32_t x0, uint32_t x1) {
    uint32_t ks2 = k0 ^ k1 ^ 0x1BD11BDAu;
    x0 += k0; x1 += k1;
#define TF_MIX(r) { x0 += x1; x1 = rotl32(x1, r); x1 ^= x0; }
    TF_MIX(13) TF_MIX(15) TF_MIX(26) TF_MIX(6)   x0 += k1;  x1 += ks2 + 1u;
    TF_MIX(17) TF_MIX(29) TF_MIX(16) TF_MIX(24)  x0 += ks2; x1 += k0 + 2u;
    TF_MIX(13) TF_MIX(15) TF_MIX(26) TF_MIX(6)   x0 += k0;  x1 += k1 + 3u;
    TF_MIX(17) TF_MIX(29) TF_MIX(16) TF_MIX(24)  x0 += k1;  x1 += ks2 + 4u;
    TF_MIX(13) TF_MIX(15) TF_MIX(26) TF_MIX(6)   x0 += ks2; x1 += k0 + 5u;
#undef TF_MIX
    return make_uint2(x0, x1);
}

// ---------------- vectorized global f32x4 reduction -------------------------
__device__ __forceinline__ void red_add_v4(float* p, float4 v) {
    asm volatile("red.global.add.v4.f32 [%0], {%1, %2, %3, %4};"
                 :: "l"(p), "f"(v.x), "f"(v.y), "f"(v.z), "f"(v.w)
                 : "memory");
}

// ---------------- GEMM1: [M,512] @ [512,128] -> [M,128], BK=16 --------------
__global__ __launch_bounds__(256) void gemm1_kernel(
    const float* __restrict__ A, const float* __restrict__ B,
    float* __restrict__ C, int M) {
    const int K = N_FEAT, N = N_HID;
    __shared__ float As[16][128];
    __shared__ float Bs[16][128];

    int row0 = blockIdx.x * 128;
    int tid = threadIdx.x;
    int tr = tid >> 4;       // 0..15
    int tc = tid & 15;       // 0..15

    float acc[8][8];
#pragma unroll
    for (int i = 0; i < 8; i++)
#pragma unroll
        for (int j = 0; j < 8; j++) acc[i][j] = 0.f;

    for (int k0 = 0; k0 < K; k0 += 16) {
        // A tile: 128 rows x 16 k = 512 float4, 2 per thread
#pragma unroll
        for (int i = 0; i < 2; i++) {
            int f = tid + i * 256;
            int m = f >> 2, kk = f & 3;
            int gr = row0 + m;
            float4 va = make_float4(0.f, 0.f, 0.f, 0.f);
            if (gr < M)
                va = *(const float4*)(A + (size_t)gr * K + k0 + kk * 4);
            As[kk * 4 + 0][m] = va.x;
            As[kk * 4 + 1][m] = va.y;
            As[kk * 4 + 2][m] = va.z;
            As[kk * 4 + 3][m] = va.w;
        }
        // B tile: 16 x 128 = 512 float4, 2 per thread
#pragma unroll
        for (int i = 0; i < 2; i++) {
            int f = tid + i * 256;
            int k = f >> 5, n4 = f & 31;
            float4 v = ((const float4*)(B + (size_t)(k0 + k) * N))[n4];
            ((float4*)&Bs[k][0])[n4] = v;
        }
        __syncthreads();
#pragma unroll
        for (int k = 0; k < 16; k++) {
            float4 a0 = ((const float4*)&As[k][tr * 8])[0];
            float4 a1 = ((const float4*)&As[k][tr * 8])[1];
            float4 b0 = ((const float4*)&Bs[k][tc * 8])[0];
            float4 b1 = ((const float4*)&Bs[k][tc * 8])[1];
            float ra[8] = {a0.x, a0.y, a0.z, a0.w, a1.x, a1.y, a1.z, a1.w};
            float rb[8] = {b0.x, b0.y, b0.z, b0.w, b1.x, b1.y, b1.z, b1.w};
#pragma unroll
            for (int i = 0; i < 8; i++)
#pragma unroll
                for (int j = 0; j < 8; j++) acc[i][j] += ra[i] * rb[j];
        }
        __syncthreads();
    }
#pragma unroll
    for (int i = 0; i < 8; i++) {
        int gr = row0 + tr * 8 + i;
        if (gr < M) {
            float4 o0 = make_float4(acc[i][0], acc[i][1], acc[i][2], acc[i][3]);
            float4 o1 = make_float4(acc[i][4], acc[i][5], acc[i][6], acc[i][7]);
            float4* cp = (float4*)(C + (size_t)gr * N + tc * 8);
            cp[0] = o0; cp[1] = o1;
        }
    }
}

// ---------------- SpMM D=128: one warp per edge, red.v4 per lane ------------
__global__ __launch_bounds__(256) void spmm128_kernel(
    const int* __restrict__ src, const int* __restrict__ dst,
    const float* __restrict__ w, const float* __restrict__ x,
    float* __restrict__ y, int E) {
    long long t = (long long)blockIdx.x * blockDim.x + threadIdx.x;
    int e = (int)(t >> 5);
    if (e >= E) return;
    int p = (int)(t & 31);
    float wt = w[e];
    int s = src[e], d = dst[e];
    float4 v = __ldg((const float4*)(x + (size_t)s * N_HID) + p);
    v.x *= wt; v.y *= wt; v.z *= wt; v.w *= wt;
    red_add_v4(y + (size_t)d * N_HID + p * 4, v);
}

// ---------------- bias + relu + dropout ------------------------------------
// Verified scheme (R4 oracle): bits = threefry2x32(0, 42, 0, idx).x
__global__ __launch_bounds__(256) void brd_kernel(
    float* __restrict__ h, const float* __restrict__ b1, int total) {
    int idx = blockIdx.x * blockDim.x + threadIdx.x;
    if (idx >= total) return;
    int j = idx & (N_HID - 1);
    float v = h[idx] + b1[j];
    v = fmaxf(v, 0.f);

    uint2 r = threefry2x32(0u, 42u, 0u, (uint32_t)idx);
    uint32_t bits = r.x;

    float u = __uint_as_float((bits >> 9) | 0x3f800000u) - 1.0f;
    h[idx] = (u < 0.5f) ? v * 2.0f : 0.0f;
}

// ---------------- GEMM2: [M,128] @ [128,40] -> [M,40], register-blocked -----
// block: 128 nodes x 40 classes; thread: 2 nodes x 10 classes.
// dynamic smem: Ws[128*40] + Hs[128][132] (padded stride vs bank conflicts)
#define G2_NODES 128
#define G2_HSTRIDE 132
__global__ __launch_bounds__(256) void gemm2_kernel(
    const float* __restrict__ H, const float* __restrict__ W2,
    float* __restrict__ out, int M) {
    extern __shared__ float sm[];
    float* Ws = sm;                      // 5120 floats
    float* Hs = sm + N_HID * N_CLASS;    // 128*132 floats

    int tid = threadIdx.x;
    int node0 = blockIdx.x * G2_NODES;

    for (int i = tid; i < N_HID * N_CLASS; i += 256) Ws[i] = W2[i];

    // H tile: 128 rows x 32 float4
    for (int f = tid; f < G2_NODES * 32; f += 256) {
        int row = f >> 5, c4 = f & 31;
        float4 v = make_float4(0.f, 0.f, 0.f, 0.f);
        int gr = node0 + row;
        if (gr < M) v = *(const float4*)(H + (size_t)gr * N_HID + c4 * 4);
        ((float4*)(Hs + row * G2_HSTRIDE))[c4] = v;
    }
    __syncthreads();

    int na = tid >> 2;             // 0..63
    int nb = na + 64;
    int c0 = (tid & 3) * 10;       // 0,10,20,30

    float accA[10], accB[10];
#pragma unroll
    for (int j = 0; j < 10; j++) { accA[j] = 0.f; accB[j] = 0.f; }

    const float* ha_p = Hs + na * G2_HSTRIDE;
    const float* hb_p = Hs + nb * G2_HSTRIDE;
#pragma unroll 4
    for (int k = 0; k < N_HID; k++) {
        float ha = ha_p[k];
        float hb = hb_p[k];
        const float* wr = Ws + k * N_CLASS + c0;
#pragma unroll
        for (int j = 0; j < 10; j++) {
            float wv = wr[j];
            accA[j] += ha * wv;
            accB[j] += hb * wv;
        }
    }

    int ga = node0 + na, gb = node0 + nb;
    if (ga < M) {
        float* o = out + (size_t)ga * N_CLASS + c0;
#pragma unroll
        for (int j = 0; j < 10; j++) o[j] = accA[j];
    }
    if (gb < M) {
        float* o = out + (size_t)gb * N_CLASS + c0;
#pragma unroll
        for (int j = 0; j < 10; j++) o[j] = accB[j];
    }
}

// ---------------- SpMM D=40: thread per (edge, float4 chunk) ----------------
__global__ __launch_bounds__(256) void spmm40_kernel(
    const int* __restrict__ src, const int* __restrict__ dst,
    const float* __restrict__ w, const float* __restrict__ x,
    float* __restrict__ y, int E) {
    long long t = (long long)blockIdx.x * blockDim.x + threadIdx.x;
    if (t >= (long long)E * 10) return;
    int e = (int)(t / 10);
    int c4 = (int)(t % 10);
    float wt = w[e];
    int s = src[e], d = dst[e];
    float4 v = __ldg((const float4*)(x + (size_t)s * N_CLASS) + c4);
    v.x *= wt; v.y *= wt; v.z *= wt; v.w *= wt;
    red_add_v4(y + (size_t)d * N_CLASS + c4 * 4, v);
}

// ---------------- bias + log_softmax (one warp per node) --------------------
__global__ __launch_bounds__(256) void lsm_kernel(
    float* __restrict__ out, const float* __restrict__ b2, int M) {
    int node = blockIdx.x * 8 + (threadIdx.x >> 5);
    int lane = threadIdx.x & 31;
    if (node >= M) return;
    float* row = out + (size_t)node * N_CLASS;
    float v0 = row[lane] + b2[lane];
    float v1 = (lane < N_CLASS - 32) ? row[32 + lane] + b2[32 + lane] : -3.402823466e38f;
    float m = fmaxf(v0, v1);
#pragma unroll
    for (int o = 16; o > 0; o >>= 1) m = fmaxf(m, __shfl_xor_sync(0xffffffffu, m, o));
    float s = expf(v0 - m) + ((lane < N_CLASS - 32) ? expf(v1 - m) : 0.f);
#pragma unroll
    for (int o = 16; o > 0; o >>= 1) s += __shfl_xor_sync(0xffffffffu, s, o);
    float lse = m + logf(s);
    row[lane] = v0 - lse;
    if (lane < N_CLASS - 32) row[32 + lane] = v1 - lse;
}

// ---------------- launcher ---------------------------------------------------
extern "C" void kernel_launch(void* const* d_in, const int* in_sizes, int n_in,
                              void* d_out, int out_size) {
    const float* feature = (const float*)d_in[0];
    const int*   esrc    = (const int*)d_in[1];
    const int*   edst    = (const int*)d_in[2];
    const float* ew      = (const float*)d_in[3];
    const float* W1      = (const float*)d_in[4];
    const float* b1      = (const float*)d_in[5];
    const float* W2      = (const float*)d_in[6];
    const float* b2      = (const float*)d_in[7];
    float* out = (float*)d_out;

    int M = in_sizes[0] / N_FEAT;   // 100000
    int E = in_sizes[1];            // 3200000

    float *xw1, *h, *hw2;
    cudaGetSymbolAddress((void**)&xw1, g_xw1);
    cudaGetSymbolAddress((void**)&h,   g_h);
    cudaGetSymbolAddress((void**)&hw2, g_hw2);

    const int g2_smem = (N_HID * N_CLASS + G2_NODES * G2_HSTRIDE) * sizeof(float);
    cudaFuncSetAttribute(gemm2_kernel,
                         cudaFuncAttributeMaxDynamicSharedMemorySize, g2_smem);

    // layer 1
    gemm1_kernel<<<(M + 127) / 128, 256>>>(feature, W1, xw1, M);
    cudaMemsetAsync(h, 0, sizeof(float) * (size_t)M * N_HID, 0);
    {
        long long work = (long long)E * 32;
        int blocks = (int)((work + 255) / 256);
        spmm128_kernel<<<blocks, 256>>>(esrc, edst, ew, xw1, h, E);
    }
    brd_kernel<<<(M * N_HID + 255) / 256, 256>>>(h, b1, M * N_HID);

    // layer 2
    gemm2_kernel<<<(M + G2_NODES - 1) / G2_NODES, 256, g2_smem>>>(h, W2, hw2, M);
    cudaMemsetAsync(out, 0, sizeof(float) * (size_t)M * N_CLASS, 0);
    {
        long long work = (long long)E * 10;
        spmm40_kernel<<<(int)((work + 255) / 256), 256>>>(esrc, edst, ew, hw2, out, E);
    }
    lsm_kernel<<<(M + 7) / 8, 256>>>(out, b2, M);
}

// round 7
// speedup vs baseline: 1.5560x; 1.3344x over previous
#include <cuda_runtime.h>
#include <cuda_bf16.h>
#include <stdint.h>

#define N_NODES 100000
#define N_FEAT  512
#define N_HID   128
#define N_CLASS 40

// ---------------- scratch (device globals; no allocations allowed) ----------
__device__ float g_xw1[(size_t)N_NODES * N_HID];    // X @ W1
__device__ float g_h  [(size_t)N_NODES * N_HID];    // spmm1 accum -> hidden
__device__ float g_hw2[(size_t)N_NODES * N_CLASS];  // h @ W2

// ---------------- Threefry-2x32-20 -----------------------------------------
__device__ __forceinline__ uint32_t rotl32(uint32_t x, int d) {
    return __funnelshift_l(x, x, d);
}

__device__ __forceinline__ uint2 threefry2x32(uint32_t k0, uint32_t k1,
                                              uint32_t x0, uint32_t x1) {
    uint32_t ks2 = k0 ^ k1 ^ 0x1BD11BDAu;
    x0 += k0; x1 += k1;
#define TF_MIX(r) { x0 += x1; x1 = rotl32(x1, r); x1 ^= x0; }
    TF_MIX(13) TF_MIX(15) TF_MIX(26) TF_MIX(6)   x0 += k1;  x1 += ks2 + 1u;
    TF_MIX(17) TF_MIX(29) TF_MIX(16) TF_MIX(24)  x0 += ks2; x1 += k0 + 2u;
    TF_MIX(13) TF_MIX(15) TF_MIX(26) TF_MIX(6)   x0 += k0;  x1 += k1 + 3u;
    TF_MIX(17) TF_MIX(29) TF_MIX(16) TF_MIX(24)  x0 += k1;  x1 += ks2 + 4u;
    TF_MIX(13) TF_MIX(15) TF_MIX(26) TF_MIX(6)   x0 += ks2; x1 += k0 + 5u;
#undef TF_MIX
    return make_uint2(x0, x1);
}

// ---------------- vectorized global f32x4 reduction -------------------------
__device__ __forceinline__ void red_add_v4(float* p, float4 v) {
    asm volatile("red.global.add.v4.f32 [%0], {%1, %2, %3, %4};"
                 :: "l"(p), "f"(v.x), "f"(v.y), "f"(v.z), "f"(v.w)
                 : "memory");
}

__device__ __forceinline__ uint32_t f2tf32(float x) {
    uint32_t r;
    asm("cvt.rna.tf32.f32 %0, %1;" : "=r"(r) : "f"(x));
    return r;
}

// ---------------- GEMM1 (tensor cores, tf32): [M,512]@[512,128] -------------
// CTA tile 128x128, BK=32. 8 warps (4x2): warp tile 32x64 = 2x8 m16n8k8 mmas.
// As stride 36 (banks 4r+c bijective), Bs stride 136 (banks 8r+c bijective).
#define G1_AS 36
#define G1_BS 136
__global__ __launch_bounds__(256) void gemm1_tc_kernel(
    const float* __restrict__ A, const float* __restrict__ B,
    float* __restrict__ C, int M) {
    __shared__ uint32_t As[128][G1_AS];
    __shared__ uint32_t Bs[32][G1_BS];

    int tid = threadIdx.x, lane = tid & 31, wid = tid >> 5;
    int warp_m = wid & 3, warp_n = wid >> 2;
    int row0 = blockIdx.x * 128;

    float c[2][8][4];
#pragma unroll
    for (int mt = 0; mt < 2; mt++)
#pragma unroll
        for (int nt = 0; nt < 8; nt++)
#pragma unroll
            for (int i = 0; i < 4; i++) c[mt][nt][i] = 0.f;

    for (int k0 = 0; k0 < N_FEAT; k0 += 32) {
        // A tile: 128 rows x 32 k = 1024 float4, 4 per thread
#pragma unroll
        for (int i = 0; i < 4; i++) {
            int f = tid + i * 256;
            int r = f >> 3, c4 = f & 7;
            int gr = row0 + r;
            float4 v = make_float4(0.f, 0.f, 0.f, 0.f);
            if (gr < M) v = *(const float4*)(A + (size_t)gr * N_FEAT + k0 + c4 * 4);
            As[r][c4 * 4 + 0] = f2tf32(v.x);
            As[r][c4 * 4 + 1] = f2tf32(v.y);
            As[r][c4 * 4 + 2] = f2tf32(v.z);
            As[r][c4 * 4 + 3] = f2tf32(v.w);
        }
        // B tile: 32 rows x 128 = 1024 float4, 4 per thread
#pragma unroll
        for (int i = 0; i < 4; i++) {
            int f = tid + i * 256;
            int r = f >> 5, c4 = f & 31;
            float4 v = *(const float4*)(B + (size_t)(k0 + r) * N_HID + c4 * 4);
            Bs[r][c4 * 4 + 0] = f2tf32(v.x);
            Bs[r][c4 * 4 + 1] = f2tf32(v.y);
            Bs[r][c4 * 4 + 2] = f2tf32(v.z);
            Bs[r][c4 * 4 + 3] = f2tf32(v.w);
        }
        __syncthreads();

#pragma unroll
        for (int kk = 0; kk < 4; kk++) {
            uint32_t af[2][4], bf[8][2];
            int colb = kk * 8 + (lane & 3);
#pragma unroll
            for (int mt = 0; mt < 2; mt++) {
                int r = warp_m * 32 + mt * 16 + (lane >> 2);
                af[mt][0] = As[r][colb];
                af[mt][1] = As[r + 8][colb];
                af[mt][2] = As[r][colb + 4];
                af[mt][3] = As[r + 8][colb + 4];
            }
            int rowb = kk * 8 + (lane & 3);
#pragma unroll
            for (int nt = 0; nt < 8; nt++) {
                int cn = warp_n * 64 + nt * 8 + (lane >> 2);
                bf[nt][0] = Bs[rowb][cn];
                bf[nt][1] = Bs[rowb + 4][cn];
            }
#pragma unroll
            for (int mt = 0; mt < 2; mt++)
#pragma unroll
                for (int nt = 0; nt < 8; nt++) {
                    asm volatile(
                        "mma.sync.aligned.m16n8k8.row.col.f32.tf32.tf32.f32 "
                        "{%0,%1,%2,%3},{%4,%5,%6,%7},{%8,%9},{%0,%1,%2,%3};"
                        : "+f"(c[mt][nt][0]), "+f"(c[mt][nt][1]),
                          "+f"(c[mt][nt][2]), "+f"(c[mt][nt][3])
                        : "r"(af[mt][0]), "r"(af[mt][1]),
                          "r"(af[mt][2]), "r"(af[mt][3]),
                          "r"(bf[nt][0]), "r"(bf[nt][1]));
                }
        }
        __syncthreads();
    }

    // epilogue
#pragma unroll
    for (int mt = 0; mt < 2; mt++) {
        int r = row0 + warp_m * 32 + mt * 16 + (lane >> 2);
#pragma unroll
        for (int nt = 0; nt < 8; nt++) {
            int cn = warp_n * 64 + nt * 8 + 2 * (lane & 3);
            if (r < M)
                *(float2*)(C + (size_t)r * N_HID + cn) =
                    make_float2(c[mt][nt][0], c[mt][nt][1]);
            if (r + 8 < M)
                *(float2*)(C + (size_t)(r + 8) * N_HID + cn) =
                    make_float2(c[mt][nt][2], c[mt][nt][3]);
        }
    }
}

// ---------------- SpMM D=128: one warp per edge, red.v4 per lane ------------
__global__ __launch_bounds__(256) void spmm128_kernel(
    const int* __restrict__ src, const int* __restrict__ dst,
    const float* __restrict__ w, const float* __restrict__ x,
    float* __restrict__ y, int E) {
    long long t = (long long)blockIdx.x * blockDim.x + threadIdx.x;
    int e = (int)(t >> 5);
    if (e >= E) return;
    int p = (int)(t & 31);
    float wt = w[e];
    int s = src[e], d = dst[e];
    float4 v = __ldg((const float4*)(x + (size_t)s * N_HID) + p);
    v.x *= wt; v.y *= wt; v.z *= wt; v.w *= wt;
    red_add_v4(y + (size_t)d * N_HID + p * 4, v);
}

// ---------------- bias + relu + dropout ------------------------------------
// Verified scheme (R4 oracle): bits = threefry2x32(0, 42, 0, idx).x
__global__ __launch_bounds__(256) void brd_kernel(
    float* __restrict__ h, const float* __restrict__ b1, int total) {
    int idx = blockIdx.x * blockDim.x + threadIdx.x;
    if (idx >= total) return;
    int j = idx & (N_HID - 1);
    float v = h[idx] + b1[j];
    v = fmaxf(v, 0.f);

    uint2 r = threefry2x32(0u, 42u, 0u, (uint32_t)idx);
    uint32_t bits = r.x;

    float u = __uint_as_float((bits >> 9) | 0x3f800000u) - 1.0f;
    h[idx] = (u < 0.5f) ? v * 2.0f : 0.0f;
}

// ---------------- GEMM2: [M,128] @ [128,40] -> [M,40], register-blocked -----
#define G2_NODES 128
#define G2_HSTRIDE 132
__global__ __launch_bounds__(256) void gemm2_kernel(
    const float* __restrict__ H, const float* __restrict__ W2,
    float* __restrict__ out, int M) {
    extern __shared__ float sm[];
    float* Ws = sm;                      // 5120 floats
    float* Hs = sm + N_HID * N_CLASS;    // 128*132 floats

    int tid = threadIdx.x;
    int node0 = blockIdx.x * G2_NODES;

    for (int i = tid; i < N_HID * N_CLASS; i += 256) Ws[i] = W2[i];

    for (int f = tid; f < G2_NODES * 32; f += 256) {
        int row = f >> 5, c4 = f & 31;
        float4 v = make_float4(0.f, 0.f, 0.f, 0.f);
        int gr = node0 + row;
        if (gr < M) v = *(const float4*)(H + (size_t)gr * N_HID + c4 * 4);
        ((float4*)(Hs + row * G2_HSTRIDE))[c4] = v;
    }
    __syncthreads();

    int na = tid >> 2;             // 0..63
    int nb = na + 64;
    int c0 = (tid & 3) * 10;       // 0,10,20,30

    float accA[10], accB[10];
#pragma unroll
    for (int j = 0; j < 10; j++) { accA[j] = 0.f; accB[j] = 0.f; }

    const float* ha_p = Hs + na * G2_HSTRIDE;
    const float* hb_p = Hs + nb * G2_HSTRIDE;
#pragma unroll 4
    for (int k = 0; k < N_HID; k++) {
        float ha = ha_p[k];
        float hb = hb_p[k];
        const float* wr = Ws + k * N_CLASS + c0;
#pragma unroll
        for (int j = 0; j < 10; j++) {
            float wv = wr[j];
            accA[j] += ha * wv;
            accB[j] += hb * wv;
        }
    }

    int ga = node0 + na, gb = node0 + nb;
    if (ga < M) {
        float* o = out + (size_t)ga * N_CLASS + c0;
#pragma unroll
        for (int j = 0; j < 10; j++) o[j] = accA[j];
    }
    if (gb < M) {
        float* o = out + (size_t)gb * N_CLASS + c0;
#pragma unroll
        for (int j = 0; j < 10; j++) o[j] = accB[j];
    }
}

// ---------------- SpMM D=40: thread per (edge, float4 chunk) ----------------
__global__ __launch_bounds__(256) void spmm40_kernel(
    const int* __restrict__ src, const int* __restrict__ dst,
    const float* __restrict__ w, const float* __restrict__ x,
    float* __restrict__ y, int E) {
    long long t = (long long)blockIdx.x * blockDim.x + threadIdx.x;
    if (t >= (long long)E * 10) return;
    int e = (int)(t / 10);
    int c4 = (int)(t % 10);
    float wt = w[e];
    int s = src[e], d = dst[e];
    float4 v = __ldg((const float4*)(x + (size_t)s * N_CLASS) + c4);
    v.x *= wt; v.y *= wt; v.z *= wt; v.w *= wt;
    red_add_v4(y + (size_t)d * N_CLASS + c4 * 4, v);
}

// ---------------- bias + log_softmax (one warp per node) --------------------
__global__ __launch_bounds__(256) void lsm_kernel(
    float* __restrict__ out, const float* __restrict__ b2, int M) {
    int node = blockIdx.x * 8 + (threadIdx.x >> 5);
    int lane = threadIdx.x & 31;
    if (node >= M) return;
    float* row = out + (size_t)node * N_CLASS;
    float v0 = row[lane] + b2[lane];
    float v1 = (lane < N_CLASS - 32) ? row[32 + lane] + b2[32 + lane] : -3.402823466e38f;
    float m = fmaxf(v0, v1);
#pragma unroll
    for (int o = 16; o > 0; o >>= 1) m = fmaxf(m, __shfl_xor_sync(0xffffffffu, m, o));
    float s = expf(v0 - m) + ((lane < N_CLASS - 32) ? expf(v1 - m) : 0.f);
#pragma unroll
    for (int o = 16; o > 0; o >>= 1) s += __shfl_xor_sync(0xffffffffu, s, o);
    float lse = m + logf(s);
    row[lane] = v0 - lse;
    if (lane < N_CLASS - 32) row[32 + lane] = v1 - lse;
}

// ---------------- launcher ---------------------------------------------------
extern "C" void kernel_launch(void* const* d_in, const int* in_sizes, int n_in,
                              void* d_out, int out_size) {
    const float* feature = (const float*)d_in[0];
    const int*   esrc    = (const int*)d_in[1];
    const int*   edst    = (const int*)d_in[2];
    const float* ew      = (const float*)d_in[3];
    const float* W1      = (const float*)d_in[4];
    const float* b1      = (const float*)d_in[5];
    const float* W2      = (const float*)d_in[6];
    const float* b2      = (const float*)d_in[7];
    float* out = (float*)d_out;

    int M = in_sizes[0] / N_FEAT;   // 100000
    int E = in_sizes[1];            // 3200000

    float *xw1, *h, *hw2;
    cudaGetSymbolAddress((void**)&xw1, g_xw1);
    cudaGetSymbolAddress((void**)&h,   g_h);
    cudaGetSymbolAddress((void**)&hw2, g_hw2);

    const int g2_smem = (N_HID * N_CLASS + G2_NODES * G2_HSTRIDE) * sizeof(float);
    cudaFuncSetAttribute(gemm2_kernel,
                         cudaFuncAttributeMaxDynamicSharedMemorySize, g2_smem);

    // layer 1
    gemm1_tc_kernel<<<(M + 127) / 128, 256>>>(feature, W1, xw1, M);
    cudaMemsetAsync(h, 0, sizeof(float) * (size_t)M * N_HID, 0);
    {
        long long work = (long long)E * 32;
        int blocks = (int)((work + 255) / 256);
        spmm128_kernel<<<blocks, 256>>>(esrc, edst, ew, xw1, h, E);
    }
    brd_kernel<<<(M * N_HID + 255) / 256, 256>>>(h, b1, M * N_HID);

    // layer 2
    gemm2_kernel<<<(M + G2_NODES - 1) / G2_NODES, 256, g2_smem>>>(h, W2, hw2, M);
    cudaMemsetAsync(out, 0, sizeof(float) * (size_t)M * N_CLASS, 0);
    {
        long long work = (long long)E * 10;
        spmm40_kernel<<<(int)((work + 255) / 256), 256>>>(esrc, edst, ew, hw2, out, E);
    }
    lsm_kernel<<<(M + 7) / 8, 256>>>(out, b2, M);
}

// round 8
// speedup vs baseline: 2.0147x; 1.2948x over previous
#include <cuda_runtime.h>
#include <cuda_bf16.h>
#include <stdint.h>

#define N_NODES 100000
#define N_FEAT  512
#define N_HID   128
#define N_CLASS 40
#define N_EDGES_MAX 3200000

// ---------------- scratch (device globals; no allocations allowed) ----------
__device__ float g_xw1[(size_t)N_NODES * N_HID];    // X @ W1
__device__ float g_h  [(size_t)N_NODES * N_HID];    // hidden after layer 1
__device__ float g_hw2[(size_t)N_NODES * N_CLASS];  // h @ W2
__device__ int   g_deg[N_NODES];
__device__ int   g_off[N_NODES + 1];
__device__ int   g_cur[N_NODES];
__device__ int   g_srcs[N_EDGES_MAX];               // dst-sorted src
__device__ float g_ews [N_EDGES_MAX];               // dst-sorted weight

// ---------------- Threefry-2x32-20 -----------------------------------------
__device__ __forceinline__ uint32_t rotl32(uint32_t x, int d) {
    return __funnelshift_l(x, x, d);
}

__device__ __forceinline__ uint2 threefry2x32(uint32_t k0, uint32_t k1,
                                              uint32_t x0, uint32_t x1) {
    uint32_t ks2 = k0 ^ k1 ^ 0x1BD11BDAu;
    x0 += k0; x1 += k1;
#define TF_MIX(r) { x0 += x1; x1 = rotl32(x1, r); x1 ^= x0; }
    TF_MIX(13) TF_MIX(15) TF_MIX(26) TF_MIX(6)   x0 += k1;  x1 += ks2 + 1u;
    TF_MIX(17) TF_MIX(29) TF_MIX(16) TF_MIX(24)  x0 += ks2; x1 += k0 + 2u;
    TF_MIX(13) TF_MIX(15) TF_MIX(26) TF_MIX(6)   x0 += k0;  x1 += k1 + 3u;
    TF_MIX(17) TF_MIX(29) TF_MIX(16) TF_MIX(24)  x0 += k1;  x1 += ks2 + 4u;
    TF_MIX(13) TF_MIX(15) TF_MIX(26) TF_MIX(6)   x0 += ks2; x1 += k0 + 5u;
#undef TF_MIX
    return make_uint2(x0, x1);
}

__device__ __forceinline__ uint32_t f2tf32(float x) {
    uint32_t r;
    asm("cvt.rna.tf32.f32 %0, %1;" : "=r"(r) : "f"(x));
    return r;
}

// ---------------- CSR build --------------------------------------------------
__global__ __launch_bounds__(256) void hist_kernel(
    const int* __restrict__ dst, int E) {
    int e = blockIdx.x * blockDim.x + threadIdx.x;
    if (e < E) atomicAdd(&g_deg[dst[e]], 1);
}

__global__ __launch_bounds__(1024) void scan_kernel(int n) {
    __shared__ int warp_sums[32];
    int tid = threadIdx.x, lane = tid & 31, wid = tid >> 5;
    int chunk = (n + 1023) / 1024;
    int start = tid * chunk;
    int end = min(start + chunk, n);

    int local = 0;
    for (int i = start; i < end; i++) local += g_deg[i];

    int v = local;
#pragma unroll
    for (int o = 1; o < 32; o <<= 1) {
        int t = __shfl_up_sync(0xffffffffu, v, o);
        if (lane >= o) v += t;
    }
    if (lane == 31) warp_sums[wid] = v;
    __syncthreads();
    if (wid == 0) {
        int s = warp_sums[lane];
#pragma unroll
        for (int o = 1; o < 32; o <<= 1) {
            int t = __shfl_up_sync(0xffffffffu, s, o);
            if (lane >= o) s += t;
        }
        warp_sums[lane] = s;
    }
    __syncthreads();
    int ex = v - local + (wid > 0 ? warp_sums[wid - 1] : 0);

    int run = ex;
    for (int i = start; i < end; i++) {
        g_off[i] = run;
        g_cur[i] = run;
        run += g_deg[i];
    }
    if (tid == 1023) g_off[n] = run;
}

__global__ __launch_bounds__(256) void scatter_kernel(
    const int* __restrict__ src, const int* __restrict__ dst,
    const float* __restrict__ w, int E) {
    int e = blockIdx.x * blockDim.x + threadIdx.x;
    if (e >= E) return;
    int d = dst[e];
    int pos = atomicAdd(&g_cur[d], 1);
    g_srcs[pos] = src[e];
    g_ews[pos]  = w[e];
}

// ---------------- GEMM1 (tensor cores, tf32): [M,512]@[512,128] -------------
#define G1_AS 36
#define G1_BS 136
__global__ __launch_bounds__(256) void gemm1_tc_kernel(
    const float* __restrict__ A, const float* __restrict__ B,
    float* __restrict__ C, int M) {
    __shared__ uint32_t As[128][G1_AS];
    __shared__ uint32_t Bs[32][G1_BS];

    int tid = threadIdx.x, lane = tid & 31, wid = tid >> 5;
    int warp_m = wid & 3, warp_n = wid >> 2;
    int row0 = blockIdx.x * 128;

    float c[2][8][4];
#pragma unroll
    for (int mt = 0; mt < 2; mt++)
#pragma unroll
        for (int nt = 0; nt < 8; nt++)
#pragma unroll
            for (int i = 0; i < 4; i++) c[mt][nt][i] = 0.f;

    for (int k0 = 0; k0 < N_FEAT; k0 += 32) {
#pragma unroll
        for (int i = 0; i < 4; i++) {
            int f = tid + i * 256;
            int r = f >> 3, c4 = f & 7;
            int gr = row0 + r;
            float4 v = make_float4(0.f, 0.f, 0.f, 0.f);
            if (gr < M) v = *(const float4*)(A + (size_t)gr * N_FEAT + k0 + c4 * 4);
            As[r][c4 * 4 + 0] = f2tf32(v.x);
            As[r][c4 * 4 + 1] = f2tf32(v.y);
            As[r][c4 * 4 + 2] = f2tf32(v.z);
            As[r][c4 * 4 + 3] = f2tf32(v.w);
        }
#pragma unroll
        for (int i = 0; i < 4; i++) {
            int f = tid + i * 256;
            int r = f >> 5, c4 = f & 31;
            float4 v = *(const float4*)(B + (size_t)(k0 + r) * N_HID + c4 * 4);
            Bs[r][c4 * 4 + 0] = f2tf32(v.x);
            Bs[r][c4 * 4 + 1] = f2tf32(v.y);
            Bs[r][c4 * 4 + 2] = f2tf32(v.z);
            Bs[r][c4 * 4 + 3] = f2tf32(v.w);
        }
        __syncthreads();

#pragma unroll
        for (int kk = 0; kk < 4; kk++) {
            uint32_t af[2][4], bf[8][2];
            int colb = kk * 8 + (lane & 3);
#pragma unroll
            for (int mt = 0; mt < 2; mt++) {
                int r = warp_m * 32 + mt * 16 + (lane >> 2);
                af[mt][0] = As[r][colb];
                af[mt][1] = As[r + 8][colb];
                af[mt][2] = As[r][colb + 4];
                af[mt][3] = As[r + 8][colb + 4];
            }
            int rowb = kk * 8 + (lane & 3);
#pragma unroll
            for (int nt = 0; nt < 8; nt++) {
                int cn = warp_n * 64 + nt * 8 + (lane >> 2);
                bf[nt][0] = Bs[rowb][cn];
                bf[nt][1] = Bs[rowb + 4][cn];
            }
#pragma unroll
            for (int mt = 0; mt < 2; mt++)
#pragma unroll
                for (int nt = 0; nt < 8; nt++) {
                    asm volatile(
                        "mma.sync.aligned.m16n8k8.row.col.f32.tf32.tf32.f32 "
                        "{%0,%1,%2,%3},{%4,%5,%6,%7},{%8,%9},{%0,%1,%2,%3};"
                        : "+f"(c[mt][nt][0]), "+f"(c[mt][nt][1]),
                          "+f"(c[mt][nt][2]), "+f"(c[mt][nt][3])
                        : "r"(af[mt][0]), "r"(af[mt][1]),
                          "r"(af[mt][2]), "r"(af[mt][3]),
                          "r"(bf[nt][0]), "r"(bf[nt][1]));
                }
        }
        __syncthreads();
    }

#pragma unroll
    for (int mt = 0; mt < 2; mt++) {
        int r = row0 + warp_m * 32 + mt * 16 + (lane >> 2);
#pragma unroll
        for (int nt = 0; nt < 8; nt++) {
            int cn = warp_n * 64 + nt * 8 + 2 * (lane & 3);
            if (r < M)
                *(float2*)(C + (size_t)r * N_HID + cn) =
                    make_float2(c[mt][nt][0], c[mt][nt][1]);
            if (r + 8 < M)
                *(float2*)(C + (size_t)(r + 8) * N_HID + cn) =
                    make_float2(c[mt][nt][2], c[mt][nt][3]);
        }
    }
}

// ---------------- SpMM1 CSR (warp/node) + fused bias/relu/dropout -----------
__global__ __launch_bounds__(256) void spmm128_csr_kernel(
    const float* __restrict__ x, const float* __restrict__ b1,
    float* __restrict__ h, int M) {
    int node = blockIdx.x * 8 + (threadIdx.x >> 5);
    if (node >= M) return;
    int lane = threadIdx.x & 31;
    int beg = g_off[node], end = g_off[node + 1];

    float4 acc = make_float4(0.f, 0.f, 0.f, 0.f);
    for (int i = beg; i < end; i++) {
        int s = __ldg(&g_srcs[i]);
        float wt = __ldg(&g_ews[i]);
        float4 v = __ldg((const float4*)(x + (size_t)s * N_HID) + lane);
        acc.x += wt * v.x; acc.y += wt * v.y;
        acc.z += wt * v.z; acc.w += wt * v.w;
    }
    float4 bv = __ldg((const float4*)b1 + lane);
    float vals[4] = {acc.x + bv.x, acc.y + bv.y, acc.z + bv.z, acc.w + bv.w};
    uint32_t base = (uint32_t)node * N_HID + lane * 4;
#pragma unroll
    for (int j = 0; j < 4; j++) {
        float v = fmaxf(vals[j], 0.f);
        uint2 r = threefry2x32(0u, 42u, 0u, base + j);
        float u = __uint_as_float((r.x >> 9) | 0x3f800000u) - 1.0f;
        vals[j] = (u < 0.5f) ? v * 2.0f : 0.0f;
    }
    *((float4*)(h + (size_t)node * N_HID) + lane) =
        make_float4(vals[0], vals[1], vals[2], vals[3]);
}

// ---------------- GEMM2: [M,128] @ [128,40] -> [M,40], register-blocked -----
#define G2_NODES 128
#define G2_HSTRIDE 132
__global__ __launch_bounds__(256) void gemm2_kernel(
    const float* __restrict__ H, const float* __restrict__ W2,
    float* __restrict__ out, int M) {
    extern __shared__ float sm[];
    float* Ws = sm;
    float* Hs = sm + N_HID * N_CLASS;

    int tid = threadIdx.x;
    int node0 = blockIdx.x * G2_NODES;

    for (int i = tid; i < N_HID * N_CLASS; i += 256) Ws[i] = W2[i];

    for (int f = tid; f < G2_NODES * 32; f += 256) {
        int row = f >> 5, c4 = f & 31;
        float4 v = make_float4(0.f, 0.f, 0.f, 0.f);
        int gr = node0 + row;
        if (gr < M) v = *(const float4*)(H + (size_t)gr * N_HID + c4 * 4);
        ((float4*)(Hs + row * G2_HSTRIDE))[c4] = v;
    }
    __syncthreads();

    int na = tid >> 2;
    int nb = na + 64;
    int c0 = (tid & 3) * 10;

    float accA[10], accB[10];
#pragma unroll
    for (int j = 0; j < 10; j++) { accA[j] = 0.f; accB[j] = 0.f; }

    const float* ha_p = Hs + na * G2_HSTRIDE;
    const float* hb_p = Hs + nb * G2_HSTRIDE;
#pragma unroll 4
    for (int k = 0; k < N_HID; k++) {
        float ha = ha_p[k];
        float hb = hb_p[k];
        const float* wr = Ws + k * N_CLASS + c0;
#pragma unroll
        for (int j = 0; j < 10; j++) {
            float wv = wr[j];
            accA[j] += ha * wv;
            accB[j] += hb * wv;
        }
    }

    int ga = node0 + na, gb = node0 + nb;
    if (ga < M) {
        float* o = out + (size_t)ga * N_CLASS + c0;
#pragma unroll
        for (int j = 0; j < 10; j++) o[j] = accA[j];
    }
    if (gb < M) {
        float* o = out + (size_t)gb * N_CLASS + c0;
#pragma unroll
        for (int j = 0; j < 10; j++) o[j] = accB[j];
    }
}

// ---------------- SpMM2 CSR: thread per (node, float4 chunk of 10) ----------
__global__ __launch_bounds__(256) void spmm40_csr_kernel(
    const float* __restrict__ x, float* __restrict__ y, int M) {
    long long t = (long long)blockIdx.x * blockDim.x + threadIdx.x;
    if (t >= (long long)M * 10) return;
    int node = (int)(t / 10);
    int c4 = (int)(t % 10);
    int beg = g_off[node], end = g_off[node + 1];

    float4 acc = make_float4(0.f, 0.f, 0.f, 0.f);
    for (int i = beg; i < end; i++) {
        int s = __ldg(&g_srcs[i]);
        float wt = __ldg(&g_ews[i]);
        float4 v = __ldg((const float4*)(x + (size_t)s * N_CLASS) + c4);
        acc.x += wt * v.x; acc.y += wt * v.y;
        acc.z += wt * v.z; acc.w += wt * v.w;
    }
    *((float4*)(y + (size_t)node * N_CLASS) + c4) = acc;
}

// ---------------- bias + log_softmax (one warp per node) --------------------
__global__ __launch_bounds__(256) void lsm_kernel(
    float* __restrict__ out, const float* __restrict__ b2, int M) {
    int node = blockIdx.x * 8 + (threadIdx.x >> 5);
    int lane = threadIdx.x & 31;
    if (node >= M) return;
    float* row = out + (size_t)node * N_CLASS;
    float v0 = row[lane] + b2[lane];
    float v1 = (lane < N_CLASS - 32) ? row[32 + lane] + b2[32 + lane] : -3.402823466e38f;
    float m = fmaxf(v0, v1);
#pragma unroll
    for (int o = 16; o > 0; o >>= 1) m = fmaxf(m, __shfl_xor_sync(0xffffffffu, m, o));
    float s = expf(v0 - m) + ((lane < N_CLASS - 32) ? expf(v1 - m) : 0.f);
#pragma unroll
    for (int o = 16; o > 0; o >>= 1) s += __shfl_xor_sync(0xffffffffu, s, o);
    float lse = m + logf(s);
    row[lane] = v0 - lse;
    if (lane < N_CLASS - 32) row[32 + lane] = v1 - lse;
}

// ---------------- launcher ---------------------------------------------------
extern "C" void kernel_launch(void* const* d_in, const int* in_sizes, int n_in,
                              void* d_out, int out_size) {
    const float* feature = (const float*)d_in[0];
    const int*   esrc    = (const int*)d_in[1];
    const int*   edst    = (const int*)d_in[2];
    const float* ew      = (const float*)d_in[3];
    const float* W1      = (const float*)d_in[4];
    const float* b1      = (const float*)d_in[5];
    const float* W2      = (const float*)d_in[6];
    const float* b2      = (const float*)d_in[7];
    float* out = (float*)d_out;

    int M = in_sizes[0] / N_FEAT;   // 100000
    int E = in_sizes[1];            // 3200000

    float *xw1, *h, *hw2;
    int *deg;
    cudaGetSymbolAddress((void**)&xw1, g_xw1);
    cudaGetSymbolAddress((void**)&h,   g_h);
    cudaGetSymbolAddress((void**)&hw2, g_hw2);
    cudaGetSymbolAddress((void**)&deg, g_deg);

    const int g2_smem = (N_HID * N_CLASS + G2_NODES * G2_HSTRIDE) * sizeof(float);
    cudaFuncSetAttribute(gemm2_kernel,
                         cudaFuncAttributeMaxDynamicSharedMemorySize, g2_smem);

    // CSR build
    cudaMemsetAsync(deg, 0, sizeof(int) * N_NODES, 0);
    hist_kernel<<<(E + 255) / 256, 256>>>(edst, E);
    scan_kernel<<<1, 1024>>>(M);
    scatter_kernel<<<(E + 255) / 256, 256>>>(esrc, edst, ew, E);

    // layer 1
    gemm1_tc_kernel<<<(M + 127) / 128, 256>>>(feature, W1, xw1, M);
    spmm128_csr_kernel<<<(M + 7) / 8, 256>>>(xw1, b1, h, M);

    // layer 2
    gemm2_kernel<<<(M + G2_NODES - 1) / G2_NODES, 256, g2_smem>>>(h, W2, hw2, M);
    spmm40_csr_kernel<<<(int)(((long long)M * 10 + 255) / 256), 256>>>(hw2, out, M);
    lsm_kernel<<<(M + 7) / 8, 256>>>(out, b2, M);
}

// round 9
// speedup vs baseline: 2.1499x; 1.0671x over previous
#include <cuda_runtime.h>
#include <cuda_fp16.h>
#include <stdint.h>

#define N_NODES 100000
#define N_FEAT  512
#define N_HID   128
#define N_CLASS 40
#define N_EDGES_MAX 3200000

// ---------------- scratch (device globals; no allocations allowed) ----------
__device__ __half g_xw1h[(size_t)N_NODES * N_HID];   // X @ W1 (fp16)
__device__ float  g_h  [(size_t)N_NODES * N_HID];    // hidden after layer 1
__device__ __half g_hw2h[(size_t)N_NODES * N_CLASS]; // h @ W2 (fp16)
__device__ int    g_deg[N_NODES];
__device__ int    g_off[N_NODES + 1];
__device__ int    g_cur[N_NODES];
__device__ int    g_srcs[N_EDGES_MAX];               // dst-sorted src
__device__ float  g_ews [N_EDGES_MAX];               // dst-sorted weight

// ---------------- Threefry-2x32-20 -----------------------------------------
__device__ __forceinline__ uint32_t rotl32(uint32_t x, int d) {
    return __funnelshift_l(x, x, d);
}

__device__ __forceinline__ uint2 threefry2x32(uint32_t k0, uint32_t k1,
                                              uint32_t x0, uint32_t x1) {
    uint32_t ks2 = k0 ^ k1 ^ 0x1BD11BDAu;
    x0 += k0; x1 += k1;
#define TF_MIX(r) { x0 += x1; x1 = rotl32(x1, r); x1 ^= x0; }
    TF_MIX(13) TF_MIX(15) TF_MIX(26) TF_MIX(6)   x0 += k1;  x1 += ks2 + 1u;
    TF_MIX(17) TF_MIX(29) TF_MIX(16) TF_MIX(24)  x0 += ks2; x1 += k0 + 2u;
    TF_MIX(13) TF_MIX(15) TF_MIX(26) TF_MIX(6)   x0 += k0;  x1 += k1 + 3u;
    TF_MIX(17) TF_MIX(29) TF_MIX(16) TF_MIX(24)  x0 += k1;  x1 += ks2 + 4u;
    TF_MIX(13) TF_MIX(15) TF_MIX(26) TF_MIX(6)   x0 += ks2; x1 += k0 + 5u;
#undef TF_MIX
    return make_uint2(x0, x1);
}

__device__ __forceinline__ uint32_t f2tf32(float x) {
    uint32_t r;
    asm("cvt.rna.tf32.f32 %0, %1;" : "=r"(r) : "f"(x));
    return r;
}

// ---------------- CSR build --------------------------------------------------
__global__ __launch_bounds__(256) void hist_kernel(
    const int* __restrict__ dst, int E) {
    int e = blockIdx.x * blockDim.x + threadIdx.x;
    if (e < E) atomicAdd(&g_deg[dst[e]], 1);
}

__global__ __launch_bounds__(1024) void scan_kernel(int n) {
    __shared__ int warp_sums[32];
    int tid = threadIdx.x, lane = tid & 31, wid = tid >> 5;
    int chunk = (n + 1023) / 1024;
    int start = tid * chunk;
    int end = min(start + chunk, n);

    int local = 0;
    for (int i = start; i < end; i++) local += g_deg[i];

    int v = local;
#pragma unroll
    for (int o = 1; o < 32; o <<= 1) {
        int t = __shfl_up_sync(0xffffffffu, v, o);
        if (lane >= o) v += t;
    }
    if (lane == 31) warp_sums[wid] = v;
    __syncthreads();
    if (wid == 0) {
        int s = warp_sums[lane];
#pragma unroll
        for (int o = 1; o < 32; o <<= 1) {
            int t = __shfl_up_sync(0xffffffffu, s, o);
            if (lane >= o) s += t;
        }
        warp_sums[lane] = s;
    }
    __syncthreads();
    int ex = v - local + (wid > 0 ? warp_sums[wid - 1] : 0);

    int run = ex;
    for (int i = start; i < end; i++) {
        g_off[i] = run;
        g_cur[i] = run;
        run += g_deg[i];
    }
    if (tid == 1023) g_off[n] = run;
}

__global__ __launch_bounds__(256) void scatter_kernel(
    const int* __restrict__ src, const int* __restrict__ dst,
    const float* __restrict__ w, int E) {
    int e = blockIdx.x * blockDim.x + threadIdx.x;
    if (e >= E) return;
    int d = dst[e];
    int pos = atomicAdd(&g_cur[d], 1);
    g_srcs[pos] = src[e];
    g_ews[pos]  = w[e];
}

// ---------------- GEMM1 (tensor cores, tf32): [M,512]@[512,128] -> fp16 -----
#define G1_AS 36
#define G1_BS 136
__global__ __launch_bounds__(256) void gemm1_tc_kernel(
    const float* __restrict__ A, const float* __restrict__ B,
    __half* __restrict__ C, int M) {
    __shared__ uint32_t As[128][G1_AS];
    __shared__ uint32_t Bs[32][G1_BS];

    int tid = threadIdx.x, lane = tid & 31, wid = tid >> 5;
    int warp_m = wid & 3, warp_n = wid >> 2;
    int row0 = blockIdx.x * 128;

    float c[2][8][4];
#pragma unroll
    for (int mt = 0; mt < 2; mt++)
#pragma unroll
        for (int nt = 0; nt < 8; nt++)
#pragma unroll
            for (int i = 0; i < 4; i++) c[mt][nt][i] = 0.f;

    for (int k0 = 0; k0 < N_FEAT; k0 += 32) {
#pragma unroll
        for (int i = 0; i < 4; i++) {
            int f = tid + i * 256;
            int r = f >> 3, c4 = f & 7;
            int gr = row0 + r;
            float4 v = make_float4(0.f, 0.f, 0.f, 0.f);
            if (gr < M) v = *(const float4*)(A + (size_t)gr * N_FEAT + k0 + c4 * 4);
            As[r][c4 * 4 + 0] = f2tf32(v.x);
            As[r][c4 * 4 + 1] = f2tf32(v.y);
            As[r][c4 * 4 + 2] = f2tf32(v.z);
            As[r][c4 * 4 + 3] = f2tf32(v.w);
        }
#pragma unroll
        for (int i = 0; i < 4; i++) {
            int f = tid + i * 256;
            int r = f >> 5, c4 = f & 31;
            float4 v = *(const float4*)(B + (size_t)(k0 + r) * N_HID + c4 * 4);
            Bs[r][c4 * 4 + 0] = f2tf32(v.x);
            Bs[r][c4 * 4 + 1] = f2tf32(v.y);
            Bs[r][c4 * 4 + 2] = f2tf32(v.z);
            Bs[r][c4 * 4 + 3] = f2tf32(v.w);
        }
        __syncthreads();

#pragma unroll
        for (int kk = 0; kk < 4; kk++) {
            uint32_t af[2][4], bf[8][2];
            int colb = kk * 8 + (lane & 3);
#pragma unroll
            for (int mt = 0; mt < 2; mt++) {
                int r = warp_m * 32 + mt * 16 + (lane >> 2);
                af[mt][0] = As[r][colb];
                af[mt][1] = As[r + 8][colb];
                af[mt][2] = As[r][colb + 4];
                af[mt][3] = As[r + 8][colb + 4];
            }
            int rowb = kk * 8 + (lane & 3);
#pragma unroll
            for (int nt = 0; nt < 8; nt++) {
                int cn = warp_n * 64 + nt * 8 + (lane >> 2);
                bf[nt][0] = Bs[rowb][cn];
                bf[nt][1] = Bs[rowb + 4][cn];
            }
#pragma unroll
            for (int mt = 0; mt < 2; mt++)
#pragma unroll
                for (int nt = 0; nt < 8; nt++) {
                    asm volatile(
                        "mma.sync.aligned.m16n8k8.row.col.f32.tf32.tf32.f32 "
                        "{%0,%1,%2,%3},{%4,%5,%6,%7},{%8,%9},{%0,%1,%2,%3};"
                        : "+f"(c[mt][nt][0]), "+f"(c[mt][nt][1]),
                          "+f"(c[mt][nt][2]), "+f"(c[mt][nt][3])
                        : "r"(af[mt][0]), "r"(af[mt][1]),
                          "r"(af[mt][2]), "r"(af[mt][3]),
                          "r"(bf[nt][0]), "r"(bf[nt][1]));
                }
        }
        __syncthreads();
    }

#pragma unroll
    for (int mt = 0; mt < 2; mt++) {
        int r = row0 + warp_m * 32 + mt * 16 + (lane >> 2);
#pragma unroll
        for (int nt = 0; nt < 8; nt++) {
            int cn = warp_n * 64 + nt * 8 + 2 * (lane & 3);
            if (r < M)
                *(__half2*)(C + (size_t)r * N_HID + cn) =
                    __floats2half2_rn(c[mt][nt][0], c[mt][nt][1]);
            if (r + 8 < M)
                *(__half2*)(C + (size_t)(r + 8) * N_HID + cn) =
                    __floats2half2_rn(c[mt][nt][2], c[mt][nt][3]);
        }
    }
}

// ---------------- SpMM1 CSR (warp/node, fp16 gather) + bias/relu/dropout ----
__global__ __launch_bounds__(256) void spmm128_csr_kernel(
    const __half* __restrict__ x, const float* __restrict__ b1,
    float* __restrict__ h, int M) {
    int node = blockIdx.x * 8 + (threadIdx.x >> 5);
    if (node >= M) return;
    int lane = threadIdx.x & 31;
    int beg = g_off[node], end = g_off[node + 1];

    float4 acc = make_float4(0.f, 0.f, 0.f, 0.f);
    for (int i = beg; i < end; i++) {
        int s = __ldg(&g_srcs[i]);
        float wt = __ldg(&g_ews[i]);
        uint2 raw = __ldg((const uint2*)(x + (size_t)s * N_HID) + lane);
        float2 f01 = __half22float2(*(__half2*)&raw.x);
        float2 f23 = __half22float2(*(__half2*)&raw.y);
        acc.x += wt * f01.x; acc.y += wt * f01.y;
        acc.z += wt * f23.x; acc.w += wt * f23.y;
    }
    float4 bv = __ldg((const float4*)b1 + lane);
    float vals[4] = {acc.x + bv.x, acc.y + bv.y, acc.z + bv.z, acc.w + bv.w};
    uint32_t base = (uint32_t)node * N_HID + lane * 4;
#pragma unroll
    for (int j = 0; j < 4; j++) {
        float v = fmaxf(vals[j], 0.f);
        uint2 r = threefry2x32(0u, 42u, 0u, base + j);
        float u = __uint_as_float((r.x >> 9) | 0x3f800000u) - 1.0f;
        vals[j] = (u < 0.5f) ? v * 2.0f : 0.0f;
    }
    *((float4*)(h + (size_t)node * N_HID) + lane) =
        make_float4(vals[0], vals[1], vals[2], vals[3]);
}

// ---------------- GEMM2: [M,128]@[128,40] -> fp16, register-blocked ---------
#define G2_NODES 128
#define G2_HSTRIDE 132
__global__ __launch_bounds__(256) void gemm2_kernel(
    const float* __restrict__ H, const float* __restrict__ W2,
    __half* __restrict__ out, int M) {
    extern __shared__ float sm[];
    float* Ws = sm;
    float* Hs = sm + N_HID * N_CLASS;

    int tid = threadIdx.x;
    int node0 = blockIdx.x * G2_NODES;

    for (int i = tid; i < N_HID * N_CLASS; i += 256) Ws[i] = W2[i];

    for (int f = tid; f < G2_NODES * 32; f += 256) {
        int row = f >> 5, c4 = f & 31;
        float4 v = make_float4(0.f, 0.f, 0.f, 0.f);
        int gr = node0 + row;
        if (gr < M) v = *(const float4*)(H + (size_t)gr * N_HID + c4 * 4);
        ((float4*)(Hs + row * G2_HSTRIDE))[c4] = v;
    }
    __syncthreads();

    int na = tid >> 2;
    int nb = na + 64;
    int c0 = (tid & 3) * 10;

    float accA[10], accB[10];
#pragma unroll
    for (int j = 0; j < 10; j++) { accA[j] = 0.f; accB[j] = 0.f; }

    const float* ha_p = Hs + na * G2_HSTRIDE;
    const float* hb_p = Hs + nb * G2_HSTRIDE;
#pragma unroll 4
    for (int k = 0; k < N_HID; k++) {
        float ha = ha_p[k];
        float hb = hb_p[k];
        const float* wr = Ws + k * N_CLASS + c0;
#pragma unroll
        for (int j = 0; j < 10; j++) {
            float wv = wr[j];
            accA[j] += ha * wv;
            accB[j] += hb * wv;
        }
    }

    int ga = node0 + na, gb = node0 + nb;
    if (ga < M) {
        __half2* o = (__half2*)(out + (size_t)ga * N_CLASS + c0);
#pragma unroll
        for (int j = 0; j < 5; j++)
            o[j] = __floats2half2_rn(accA[2 * j], accA[2 * j + 1]);
    }
    if (gb < M) {
        __half2* o = (__half2*)(out + (size_t)gb * N_CLASS + c0);
#pragma unroll
        for (int j = 0; j < 5; j++)
            o[j] = __floats2half2_rn(accB[2 * j], accB[2 * j + 1]);
    }
}

// ---------------- SpMM2 CSR: thread per (node, 8-class chunk), fp16 gather --
__global__ __launch_bounds__(256) void spmm40_csr_kernel(
    const __half* __restrict__ x, float* __restrict__ y, int M) {
    long long t = (long long)blockIdx.x * blockDim.x + threadIdx.x;
    if (t >= (long long)M * 5) return;
    int node = (int)(t / 5);
    int c8 = (int)(t % 5);
    int beg = g_off[node], end = g_off[node + 1];

    float acc[8];
#pragma unroll
    for (int j = 0; j < 8; j++) acc[j] = 0.f;

    for (int i = beg; i < end; i++) {
        int s = __ldg(&g_srcs[i]);
        float wt = __ldg(&g_ews[i]);
        uint4 raw = __ldg((const uint4*)(x + (size_t)s * N_CLASS) + c8);
        float2 f0 = __half22float2(*(__half2*)&raw.x);
        float2 f1 = __half22float2(*(__half2*)&raw.y);
        float2 f2 = __half22float2(*(__half2*)&raw.z);
        float2 f3 = __half22float2(*(__half2*)&raw.w);
        acc[0] += wt * f0.x; acc[1] += wt * f0.y;
        acc[2] += wt * f1.x; acc[3] += wt * f1.y;
        acc[4] += wt * f2.x; acc[5] += wt * f2.y;
        acc[6] += wt * f3.x; acc[7] += wt * f3.y;
    }
    float* o = y + (size_t)node * N_CLASS + c8 * 8;
    *(float4*)(o + 0) = make_float4(acc[0], acc[1], acc[2], acc[3]);
    *(float4*)(o + 4) = make_float4(acc[4], acc[5], acc[6], acc[7]);
}

// ---------------- bias + log_softmax (one warp per node) --------------------
__global__ __launch_bounds__(256) void lsm_kernel(
    float* __restrict__ out, const float* __restrict__ b2, int M) {
    int node = blockIdx.x * 8 + (threadIdx.x >> 5);
    int lane = threadIdx.x & 31;
    if (node >= M) return;
    float* row = out + (size_t)node * N_CLASS;
    float v0 = row[lane] + b2[lane];
    float v1 = (lane < N_CLASS - 32) ? row[32 + lane] + b2[32 + lane] : -3.402823466e38f;
    float m = fmaxf(v0, v1);
#pragma unroll
    for (int o = 16; o > 0; o >>= 1) m = fmaxf(m, __shfl_xor_sync(0xffffffffu, m, o));
    float s = expf(v0 - m) + ((lane < N_CLASS - 32) ? expf(v1 - m) : 0.f);
#pragma unroll
    for (int o = 16; o > 0; o >>= 1) s += __shfl_xor_sync(0xffffffffu, s, o);
    float lse = m + logf(s);
    row[lane] = v0 - lse;
    if (lane < N_CLASS - 32) row[32 + lane] = v1 - lse;
}

// ---------------- launcher ---------------------------------------------------
extern "C" void kernel_launch(void* const* d_in, const int* in_sizes, int n_in,
                              void* d_out, int out_size) {
    const float* feature = (const float*)d_in[0];
    const int*   esrc    = (const int*)d_in[1];
    const int*   edst    = (const int*)d_in[2];
    const float* ew      = (const float*)d_in[3];
    const float* W1      = (const float*)d_in[4];
    const float* b1      = (const float*)d_in[5];
    const float* W2      = (const float*)d_in[6];
    const float* b2      = (const float*)d_in[7];
    float* out = (float*)d_out;

    int M = in_sizes[0] / N_FEAT;   // 100000
    int E = in_sizes[1];            // 3200000

    __half *xw1h, *hw2h;
    float *h;
    int *deg;
    cudaGetSymbolAddress((void**)&xw1h, g_xw1h);
    cudaGetSymbolAddress((void**)&h,    g_h);
    cudaGetSymbolAddress((void**)&hw2h, g_hw2h);
    cudaGetSymbolAddress((void**)&deg,  g_deg);

    const int g2_smem = (N_HID * N_CLASS + G2_NODES * G2_HSTRIDE) * sizeof(float);
    cudaFuncSetAttribute(gemm2_kernel,
                         cudaFuncAttributeMaxDynamicSharedMemorySize, g2_smem);

    // CSR build
    cudaMemsetAsync(deg, 0, sizeof(int) * N_NODES, 0);
    hist_kernel<<<(E + 255) / 256, 256>>>(edst, E);
    scan_kernel<<<1, 1024>>>(M);
    scatter_kernel<<<(E + 255) / 256, 256>>>(esrc, edst, ew, E);

    // layer 1
    gemm1_tc_kernel<<<(M + 127) / 128, 256>>>(feature, W1, xw1h, M);
    spmm128_csr_kernel<<<(M + 7) / 8, 256>>>(xw1h, b1, h, M);

    // layer 2
    gemm2_kernel<<<(M + G2_NODES - 1) / G2_NODES, 256, g2_smem>>>(h, W2, hw2h, M);
    spmm40_csr_kernel<<<(int)(((long long)M * 5 + 255) / 256), 256>>>(hw2h, out, M);
    lsm_kernel<<<(M + 7) / 8, 256>>>(out, b2, M);
}